// round 11
// baseline (speedup 1.0000x reference)
#include <cuda_runtime.h>
#include <float.h>
#include <cstdint>

#define NCH       36
#define NANCH     8400
#define NCLS      32
#define MAXDET    100
#define BATCH     64
#define NTHREADS  1024
#define CLUSTER   2
#define HALF_ANCH 4200            // anchors per CTA
#define KPT       5               // ceil(4200/1024)
#define CONF_T    0.25f
// iou > 0.45  <=>  inter > (0.45/1.45)*(A+B)   [valid: inter>0 => union>0]
#define C_HI      0.31034523f     // c*(1+~1.3e-6)
#define C_LO      0.31034442f     // c*(1-~1.3e-6)

// dynamic smem per CTA:
//   float4 box[4200] | float area[4200] | float cls[4200] | uint2 list[2][4200]
#define OFF_LIST   (6 * HALF_ANCH * 4)            // 100800 B
#define SMEM_BYTES (OFF_LIST + 2 * HALF_ANCH * 8) // 168000 B

struct alignas(16) Rec {            // winner record (broadcast-read only)
    float y1, x1, y2, x2;
    float area, cls;
    float pad0, pad1;
};

__device__ __forceinline__ uint32_t smem_u32(const void* p) {
    uint32_t a;
    asm("{ .reg .u64 t; cvta.to.shared.u64 t, %1; cvt.u32.u64 %0, t; }" : "=r"(a) : "l"(p));
    return a;
}
__device__ __forceinline__ uint32_t mapa_u32(uint32_t a, uint32_t rank) {
    uint32_t o;
    asm("mapa.shared::cluster.u32 %0, %1, %2;" : "=r"(o) : "r"(a), "r"(rank));
    return o;
}
__device__ __forceinline__ void st_cluster(uint32_t a, unsigned v) {
    asm volatile("st.shared::cluster.u32 [%0], %1;" :: "r"(a), "r"(v) : "memory");
}
// monotone float -> u32 key (bigger float => bigger key); fkey(0.0f)=0x80000000
__device__ __forceinline__ unsigned fkey(float f) {
    unsigned b = __float_as_uint(f);
    return ((int)b >= 0) ? (b | 0x80000000u) : ~b;
}

__global__ __launch_bounds__(NTHREADS, 1) __cluster_dims__(CLUSTER, 1, 1)
void yolo_nms_kernel(const float* __restrict__ in, float* __restrict__ out) {
    extern __shared__ float smem[];
    float4* sbox  = (float4*)smem;             // [4200]
    float*  sarea = smem + 4 * HALF_ANCH;      // [4200]
    float*  scls  = smem + 5 * HALF_ANCH;      // [4200]
    uint2*  list0 = (uint2*)((char*)smem + OFF_LIST);          // [4200]
    uint2*  list1 = list0 + HALF_ANCH;                          // [4200]
    __shared__ uint2 ckey[2][64];              // (key, gidx), parity-buffered
    __shared__ Rec   crec[2][64];              // winner records
    __shared__ int   cnum[MAXDET + 1];         // per-iteration alive counters
    __shared__ unsigned long long cbar;        // mbarrier, 64 arrivals/phase

    const int tid  = threadIdx.x;
    const int lane = tid & 31;
    const int wid  = tid >> 5;
    unsigned rank;
    asm("mov.u32 %0, %%cluster_ctarank;" : "=r"(rank));
    const int img   = blockIdx.x >> 1;
    const int gbase = rank * HALF_ANCH;

    const float* base = in + (size_t)img * NCH * NANCH;

    float* ob  = out + (size_t)img * MAXDET * 4;
    float* oc  = out + (size_t)BATCH * MAXDET * 4 + (size_t)img * MAXDET;
    float* osc = out + (size_t)BATCH * MAXDET * 4 + (size_t)BATCH * MAXDET + (size_t)img * MAXDET;
    float* ond = out + (size_t)BATCH * MAXDET * 4 + (size_t)BATCH * MAXDET * 2;

    const uint32_t bar_a  = smem_u32(&cbar);
    const uint32_t peer   = rank ^ 1u;
    const uint32_t r_bar  = mapa_u32(bar_a, peer);
    const uint32_t r_ckey = mapa_u32(smem_u32(&ckey[0][0]), peer);
    const uint32_t r_crec = mapa_u32(smem_u32(&crec[0][0]), peer);

    if (tid == 0) {
        asm volatile("mbarrier.init.shared.b64 [%0], %1;" :: "r"(bar_a), "r"(64u) : "memory");
    }
    if (tid <= MAXDET) cnum[tid] = 0;

    if (rank == 0) {
        for (int i = tid; i < MAXDET * 4; i += NTHREADS) ob[i] = 0.0f;
        if (tid < MAXDET) { oc[tid] = 0.0f; osc[tid] = 0.0f; }
    }
    __syncthreads();   // cnum zeroed before initial-list appends

    // ---- Phase 1: preprocess + build initial alive list (list0, cnum[0]) ----
    unsigned lk = 0u;
    int      li = gbase + tid;
    #pragma unroll
    for (int k = 0; k < KPT; k++) {
        int l = tid + k * NTHREADS;
        unsigned ku = 0u;
        int gid = gbase + l;
        if (l < HALF_ANCH) {
            float xc = base[0 * NANCH + gid];
            float yc = base[1 * NANCH + gid];
            float w  = base[2 * NANCH + gid];
            float h  = base[3 * NANCH + gid];
            float best = -FLT_MAX;
            int cls = 0;
            #pragma unroll
            for (int c = 0; c < NCLS; c++) {
                float v = base[(4 + c) * NANCH + gid];
                if (v > best) { best = v; cls = c; }   // strict > == first-max
            }
            float y1 = fminf(fmaxf(yc - 0.5f * h, 0.0f), 1.0f);
            float x1 = fminf(fmaxf(xc - 0.5f * w, 0.0f), 1.0f);
            float y2 = fminf(fmaxf(yc + 0.5f * h, 0.0f), 1.0f);
            float x2 = fminf(fmaxf(xc + 0.5f * w, 0.0f), 1.0f);
            sbox[l]  = make_float4(y1, x1, y2, x2);
            sarea[l] = (y2 - y1) * (x2 - x1);
            scls[l]  = (float)cls;
            // masked (<CONF) anchors are dead from the start (ref: -1 forever)
            if (best >= CONF_T) ku = fkey(best);   // > 0x80000000 for best>0
        }
        // ascending k => ascending gid, so '>' keeps first occurrence
        if (ku > lk) { lk = ku; li = gid; }
        // append alive entries to initial list (order-free; argmax is explicit)
        unsigned mask = __ballot_sync(0xFFFFFFFFu, ku != 0u);
        unsigned bpos = 0;
        if (lane == 0 && mask) bpos = (unsigned)atomicAdd(&cnum[0], __popc(mask));
        bpos = __shfl_sync(0xFFFFFFFFu, bpos, 0);
        if (ku != 0u)
            list0[bpos + __popc(mask & ((1u << lane) - 1u))] = make_uint2(ku, (unsigned)gid);
    }
    __syncthreads();
    asm volatile("barrier.cluster.arrive.aligned;" ::: "memory");
    asm volatile("barrier.cluster.wait.aligned;"   ::: "memory");

    int ndet = 0;
    for (int d = 0; d < MAXDET; d++) {
        const int p = d & 1;

        // ---- stage 1: warp argmax via redux (key desc, gidx asc) ----
        unsigned wu = __reduce_max_sync(0xFFFFFFFFu, lk);
        unsigned ci = (lk == wu) ? (unsigned)li : 0xFFFFFFFFu;
        unsigned wg = __reduce_min_sync(0xFFFFFFFFu, ci);

        // winner lane publishes to BOTH CTAs, arrives on both barriers.
        // (li values are unique per lane, so exactly one lane matches.)
        if (lk == wu && (unsigned)li == wg) {
            int l = (int)wg - gbase;
            l = (unsigned)l < HALF_ANCH ? l : 0;   // only key==0 case; data unused
            float4 wb = sbox[l];
            float  wa = sarea[l];
            float  wc = scls[l];
            int slot = (int)rank * 32 + wid;
            ckey[p][slot] = make_uint2(wu, wg);
            Rec rc; rc.y1 = wb.x; rc.x1 = wb.y; rc.y2 = wb.z; rc.x2 = wb.w;
            rc.area = wa; rc.cls = wc; rc.pad0 = 0.f; rc.pad1 = 0.f;
            crec[p][slot] = rc;
            uint32_t rk = r_ckey + (uint32_t)(p * 64 + slot) * 8u;
            st_cluster(rk + 0, wu);
            st_cluster(rk + 4, wg);
            uint32_t rr = r_crec + (uint32_t)(p * 64 + slot) * sizeof(Rec);
            st_cluster(rr + 0,  __float_as_uint(wb.x));
            st_cluster(rr + 4,  __float_as_uint(wb.y));
            st_cluster(rr + 8,  __float_as_uint(wb.z));
            st_cluster(rr + 12, __float_as_uint(wb.w));
            st_cluster(rr + 16, __float_as_uint(wa));
            st_cluster(rr + 20, __float_as_uint(wc));
            asm volatile("mbarrier.arrive.shared.b64 _, [%0];" :: "r"(bar_a) : "memory");
            asm volatile("mbarrier.arrive.release.cluster.shared::cluster.b64 _, [%0];"
                         :: "r"(r_bar) : "memory");
        }

        // ---- wait: 64 arrivals (32 local + 32 remote) ----
        // local arrives also certify: every warp finished pass d-1
        {
            unsigned done;
            asm volatile(
                "{\n\t.reg .pred q;\n\t"
                "mbarrier.try_wait.parity.acquire.cluster.shared::cta.b64 q, [%1], %2, 0x989680;\n\t"
                "selp.b32 %0, 1, 0, q;\n\t}"
                : "=r"(done) : "r"(bar_a), "r"((unsigned)p) : "memory");
            if (!done) {
                asm volatile(
                    "{\n\t.reg .pred Q1;\n\t"
                    "WL_%=:\n\t"
                    "mbarrier.try_wait.parity.acquire.cluster.shared::cta.b64 Q1, [%0], %1, 0x989680;\n\t"
                    "@Q1 bra.uni WD_%=;\n\t"
                    "bra.uni WL_%=;\n\t"
                    "WD_%=:\n\t}"
                    :: "r"(bar_a), "r"((unsigned)p) : "memory");
            }
        }

        // ---- stage 2: reduce 64 candidates (2/lane), every warp redundantly ----
        uint2 a0 = ckey[p][lane];
        uint2 a1 = ckey[p][lane + 32];
        bool pick1 = (a1.x > a0.x) || (a1.x == a0.x && a1.y < a0.y);
        unsigned mu = pick1 ? a1.x : a0.x;
        unsigned mg = pick1 ? a1.y : a0.y;
        int   mslot = pick1 ? (lane + 32) : lane;

        unsigned wu2 = __reduce_max_sync(0xFFFFFFFFu, mu);
        unsigned cg2 = (mu == wu2) ? mg : 0xFFFFFFFFu;
        unsigned wg2 = __reduce_min_sync(0xFFFFFFFFu, cg2);

        if (wu2 <= 0x80000000u) break;   // winner score <= 0 -> done (uniform)
        ndet++;

        unsigned msk = __ballot_sync(0xFFFFFFFFu, mu == wu2 && mg == wg2);
        int slot = __shfl_sync(0xFFFFFFFFu, mslot, __ffs(msk) - 1);

        const Rec* w = &crec[p][slot];     // broadcast LDS
        float4 bb = make_float4(w->y1, w->x1, w->y2, w->x2);
        float  ba = w->area;
        int    gi = (int)wg2;

        if (rank == 0 && tid == 0) {
            float sraw = (wu2 & 0x80000000u) ? __uint_as_float(wu2 & 0x7FFFFFFFu)
                                             : __uint_as_float(~wu2);
            ob[d * 4 + 0] = bb.x; ob[d * 4 + 1] = bb.y;
            ob[d * 4 + 2] = bb.z; ob[d * 4 + 3] = bb.w;
            oc[d]  = w->cls;
            osc[d] = sraw;
        }

        // ---- pass d: traverse alive list, kill, compact survivors, next argmax ----
        const uint2* lcur = p ? list1 : list0;
        uint2*       lnxt = p ? list0 : list1;
        int n = cnum[d];                    // safe: all appends preceded arrivals
        int rounds = (n + NTHREADS - 1) >> 10;

        lk = 0u;
        li = gbase + tid;
        for (int r = 0; r < rounds; r++) {
            int i = (r << 10) + tid;
            bool valid = i < n;
            uint2 e = valid ? lcur[i] : make_uint2(0u, 0u);
            bool survive = false;
            if (valid) {
                int l = (int)e.y - gbase;
                float4 b  = sbox[l];
                float  ab = sarea[l];
                float yy1 = fmaxf(bb.x, b.x);
                float xx1 = fmaxf(bb.y, b.y);
                float yy2 = fminf(bb.z, b.z);
                float xx2 = fminf(bb.w, b.w);
                float inter = fmaxf(yy2 - yy1, 0.0f) * fmaxf(xx2 - xx1, 0.0f);
                float S = ba + ab;
                bool kill = ((int)e.y == gi) || (inter > C_HI * S);
                if (!kill && !(inter < C_LO * S)) {
                    // ambiguous band: replicate reference ops exactly
                    float uni = ba + ab - inter;
                    if (uni > 0.0f) kill = (inter / uni) > 0.45f;
                }
                survive = !kill;
            }
            unsigned mask = __ballot_sync(0xFFFFFFFFu, survive);
            unsigned bpos = 0;
            if (lane == 0 && mask) bpos = (unsigned)atomicAdd(&cnum[d + 1], __popc(mask));
            bpos = __shfl_sync(0xFFFFFFFFu, bpos, 0);
            if (survive) {
                lnxt[bpos + __popc(mask & ((1u << lane) - 1u))] = e;
                if (e.x > lk || (e.x == lk && (int)e.y < li)) { lk = e.x; li = (int)e.y; }
            }
        }
    }

    if (rank == 0 && tid == 0) ond[img] = (float)ndet;

    asm volatile("barrier.cluster.arrive.aligned;" ::: "memory");
    asm volatile("barrier.cluster.wait.aligned;"   ::: "memory");
}

extern "C" void kernel_launch(void* const* d_in, const int* in_sizes, int n_in,
                              void* d_out, int out_size) {
    static bool attr_done = false;
    if (!attr_done) {
        cudaFuncSetAttribute(yolo_nms_kernel,
                             cudaFuncAttributeMaxDynamicSharedMemorySize, SMEM_BYTES);
        attr_done = true;
    }
    const float* in = (const float*)d_in[0];
    float* out = (float*)d_out;
    yolo_nms_kernel<<<BATCH * CLUSTER, NTHREADS, SMEM_BYTES>>>(in, out);
}

// round 12
// speedup vs baseline: 1.3376x; 1.3376x over previous
#include <cuda_runtime.h>
#include <float.h>
#include <cstdint>

#define NCH       36
#define NANCH     8400
#define NCLS      32
#define MAXDET    100
#define BATCH     64
#define NTHREADS  1024
#define CLUSTER   2
#define HALF_ANCH 4200            // anchors per CTA
#define KPT       5               // ceil(4200/1024)
#define CONF_T    0.25f
// iou > 0.45  <=>  inter > (0.45/1.45)*(A+B)   [valid: inter>0 => union>0]
#define C_HI      0.31034523f     // c*(1+~1.3e-6)
#define C_LO      0.31034442f     // c*(1-~1.3e-6)

// dynamic smem per CTA: float4 box[4200] + area[4200] + cls[4200]
#define SMEM_BYTES ((4 + 1 + 1) * HALF_ANCH * 4)

struct alignas(16) Rec {            // winner record (broadcast-read only)
    float y1, x1, y2, x2;
    float area, cls;
    float pad0, pad1;
};

__device__ __forceinline__ uint32_t smem_u32(const void* p) {
    uint32_t a;
    asm("{ .reg .u64 t; cvta.to.shared.u64 t, %1; cvt.u32.u64 %0, t; }" : "=r"(a) : "l"(p));
    return a;
}
__device__ __forceinline__ uint32_t mapa_u32(uint32_t a, uint32_t rank) {
    uint32_t o;
    asm("mapa.shared::cluster.u32 %0, %1, %2;" : "=r"(o) : "r"(a), "r"(rank));
    return o;
}
__device__ __forceinline__ void st_cluster(uint32_t a, unsigned v) {
    asm volatile("st.shared::cluster.u32 [%0], %1;" :: "r"(a), "r"(v) : "memory");
}
// monotone float -> u32 key (bigger float => bigger key); fkey(0.0f)=0x80000000
__device__ __forceinline__ unsigned fkey(float f) {
    unsigned b = __float_as_uint(f);
    return ((int)b >= 0) ? (b | 0x80000000u) : ~b;
}
// lexicographic "a better than b": key desc, gid asc
__device__ __forceinline__ bool lexGT(uint2 a, uint2 b) {
    return (a.x > b.x) || (a.x == b.x && a.y < b.y);
}

__global__ __launch_bounds__(NTHREADS, 1) __cluster_dims__(CLUSTER, 1, 1)
void yolo_nms_kernel(const float* __restrict__ in, float* __restrict__ out) {
    extern __shared__ float smem[];
    float4* sbox  = (float4*)smem;             // [4200]
    float*  sarea = smem + 4 * HALF_ANCH;      // [4200]
    float*  scls  = smem + 5 * HALF_ANCH;      // [4200]
    __shared__ uint2 ckey[2][128];             // parity x (64 top1 | 64 top2)
    __shared__ Rec   crec[2][128];
    __shared__ unsigned long long cbar;        // mbarrier, 64 arrivals/phase

    const int tid  = threadIdx.x;
    const int lane = tid & 31;
    const int wid  = tid >> 5;
    unsigned rank;
    asm("mov.u32 %0, %%cluster_ctarank;" : "=r"(rank));
    const int img   = blockIdx.x >> 1;
    const int gbase = rank * HALF_ANCH;

    const float* base = in + (size_t)img * NCH * NANCH;

    float* ob  = out + (size_t)img * MAXDET * 4;
    float* oc  = out + (size_t)BATCH * MAXDET * 4 + (size_t)img * MAXDET;
    float* osc = out + (size_t)BATCH * MAXDET * 4 + (size_t)BATCH * MAXDET + (size_t)img * MAXDET;
    float* ond = out + (size_t)BATCH * MAXDET * 4 + (size_t)BATCH * MAXDET * 2;

    const uint32_t bar_a  = smem_u32(&cbar);
    const uint32_t peer   = rank ^ 1u;
    const uint32_t r_bar  = mapa_u32(bar_a, peer);
    const uint32_t r_ckey = mapa_u32(smem_u32(&ckey[0][0]), peer);
    const uint32_t r_crec = mapa_u32(smem_u32(&crec[0][0]), peer);

    if (tid == 0) {
        asm volatile("mbarrier.init.shared.b64 [%0], %1;" :: "r"(bar_a), "r"(64u) : "memory");
    }

    if (rank == 0) {
        for (int i = tid; i < MAXDET * 4; i += NTHREADS) ob[i] = 0.0f;
        if (tid < MAXDET) { oc[tid] = 0.0f; osc[tid] = 0.0f; }
    }

    // ---- Phase 1: preprocess this CTA's 4200 anchors ----
    unsigned ukey[KPT];
    #pragma unroll
    for (int k = 0; k < KPT; k++) {
        int l = tid + k * NTHREADS;
        unsigned ku = 0u;
        if (l < HALF_ANCH) {
            int ga = gbase + l;
            float xc = base[0 * NANCH + ga];
            float yc = base[1 * NANCH + ga];
            float w  = base[2 * NANCH + ga];
            float h  = base[3 * NANCH + ga];
            float best = -FLT_MAX;
            int cls = 0;
            #pragma unroll
            for (int c = 0; c < NCLS; c++) {
                float v = base[(4 + c) * NANCH + ga];
                if (v > best) { best = v; cls = c; }   // strict > == first-max
            }
            float y1 = fminf(fmaxf(yc - 0.5f * h, 0.0f), 1.0f);
            float x1 = fminf(fmaxf(xc - 0.5f * w, 0.0f), 1.0f);
            float y2 = fminf(fmaxf(yc + 0.5f * h, 0.0f), 1.0f);
            float x2 = fminf(fmaxf(xc + 0.5f * w, 0.0f), 1.0f);
            sbox[l]  = make_float4(y1, x1, y2, x2);
            sarea[l] = (y2 - y1) * (x2 - x1);
            scls[l]  = (float)cls;
            // masked (<CONF) anchors dead from the start (ref: -1 forever)
            if (best >= CONF_T) ku = fkey(best);   // > 0x80000000 for best>0
        }
        ukey[k] = ku;
    }
    __syncthreads();
    asm volatile("barrier.cluster.arrive.aligned;" ::: "memory");
    asm volatile("barrier.cluster.wait.aligned;"   ::: "memory");

    // first local argmax: descending k + '>=' => lowest gid on ties
    unsigned lk = 0u;
    int      li = gbase + tid;
    #pragma unroll
    for (int k = KPT - 1; k >= 0; k--) {
        int gid = gbase + tid + k * NTHREADS;
        if (ukey[k] >= lk) { lk = ukey[k]; li = gid; }
    }

    int ndet = 0, d = 0;
    for (int e = 0; e < MAXDET && d < MAXDET; e++) {
        const int p = e & 1;

        // ---- stage 1: warp top-2 via redux ----
        unsigned wu = __reduce_max_sync(0xFFFFFFFFu, lk);
        unsigned ci = (lk == wu) ? (unsigned)li : 0xFFFFFFFFu;
        unsigned wg = __reduce_min_sync(0xFFFFFFFFu, ci);

        // winner lane recomputes its local best EXCLUDING the winner anchor
        unsigned e2k = lk; int e2i = li;
        if (lk == wu && (unsigned)li == wg) {
            int kwin = (li - gbase) >> 10;
            e2k = 0u; e2i = gbase + tid;
            #pragma unroll
            for (int k = KPT - 1; k >= 0; k--) {
                int gid = gbase + tid + k * NTHREADS;
                unsigned kv = (k == kwin) ? 0u : ukey[k];
                if (kv >= e2k) { e2k = kv; e2i = gid; }
            }
        }
        unsigned wu2 = __reduce_max_sync(0xFFFFFFFFu, e2k);
        unsigned c2  = (e2k == wu2) ? (unsigned)e2i : 0xFFFFFFFFu;
        unsigned wg2 = __reduce_min_sync(0xFFFFFFFFu, c2);

        // lane 0 publishes BOTH candidates (+records) to both CTAs, arrives
        if (lane == 0) {
            int lA = (int)wg  - gbase;
            int lB = (int)wg2 - gbase;
            float4 bA = sbox[lA]; float aA = sarea[lA]; float cA = scls[lA];
            float4 bB = sbox[lB]; float aB = sarea[lB]; float cB = scls[lB];
            int sA = (int)rank * 32 + wid;
            int sB = 64 + sA;
            ckey[p][sA] = make_uint2(wu,  wg);
            ckey[p][sB] = make_uint2(wu2, wg2);
            Rec rA; rA.y1=bA.x; rA.x1=bA.y; rA.y2=bA.z; rA.x2=bA.w; rA.area=aA; rA.cls=cA; rA.pad0=0; rA.pad1=0;
            Rec rB; rB.y1=bB.x; rB.x1=bB.y; rB.y2=bB.z; rB.x2=bB.w; rB.area=aB; rB.cls=cB; rB.pad0=0; rB.pad1=0;
            crec[p][sA] = rA;
            crec[p][sB] = rB;
            uint32_t rkA = r_ckey + (uint32_t)(p * 128 + sA) * 8u;
            uint32_t rkB = r_ckey + (uint32_t)(p * 128 + sB) * 8u;
            st_cluster(rkA + 0, wu);  st_cluster(rkA + 4, wg);
            st_cluster(rkB + 0, wu2); st_cluster(rkB + 4, wg2);
            uint32_t rrA = r_crec + (uint32_t)(p * 128 + sA) * sizeof(Rec);
            uint32_t rrB = r_crec + (uint32_t)(p * 128 + sB) * sizeof(Rec);
            st_cluster(rrA + 0,  __float_as_uint(bA.x));
            st_cluster(rrA + 4,  __float_as_uint(bA.y));
            st_cluster(rrA + 8,  __float_as_uint(bA.z));
            st_cluster(rrA + 12, __float_as_uint(bA.w));
            st_cluster(rrA + 16, __float_as_uint(aA));
            st_cluster(rrA + 20, __float_as_uint(cA));
            st_cluster(rrB + 0,  __float_as_uint(bB.x));
            st_cluster(rrB + 4,  __float_as_uint(bB.y));
            st_cluster(rrB + 8,  __float_as_uint(bB.z));
            st_cluster(rrB + 12, __float_as_uint(bB.w));
            st_cluster(rrB + 16, __float_as_uint(aB));
            st_cluster(rrB + 20, __float_as_uint(cB));
            asm volatile("mbarrier.arrive.shared.b64 _, [%0];" :: "r"(bar_a) : "memory");
            asm volatile("mbarrier.arrive.release.cluster.shared::cluster.b64 _, [%0];"
                         :: "r"(r_bar) : "memory");
        }

        // ---- wait: 64 arrivals ----
        {
            unsigned done;
            asm volatile(
                "{\n\t.reg .pred q;\n\t"
                "mbarrier.try_wait.parity.acquire.cluster.shared::cta.b64 q, [%1], %2, 0x989680;\n\t"
                "selp.b32 %0, 1, 0, q;\n\t}"
                : "=r"(done) : "r"(bar_a), "r"((unsigned)p) : "memory");
            if (!done) {
                asm volatile(
                    "{\n\t.reg .pred Q1;\n\t"
                    "WL_%=:\n\t"
                    "mbarrier.try_wait.parity.acquire.cluster.shared::cta.b64 Q1, [%0], %1, 0x989680;\n\t"
                    "@Q1 bra.uni WD_%=;\n\t"
                    "bra.uni WL_%=;\n\t"
                    "WD_%=:\n\t}"
                    :: "r"(bar_a), "r"((unsigned)p) : "memory");
            }
        }

        // ---- stage 2: global top-2 of 128 candidates (4/lane), all warps ----
        uint2 e0 = ckey[p][lane];
        uint2 e1 = ckey[p][lane + 32];
        uint2 e2 = ckey[p][lane + 64];
        uint2 e3 = ckey[p][lane + 96];
        uint2 A = lexGT(e0, e1) ? e0 : e1, B = lexGT(e0, e1) ? e1 : e0;
        uint2 C = lexGT(e2, e3) ? e2 : e3, D = lexGT(e2, e3) ? e3 : e2;
        bool ac = lexGT(A, C);
        uint2 t1 = ac ? A : C;
        uint2 t2cand1 = ac ? B : D;
        uint2 t2cand2 = ac ? C : A;
        uint2 t2 = lexGT(t2cand1, t2cand2) ? t2cand1 : t2cand2;

        unsigned ku1 = __reduce_max_sync(0xFFFFFFFFu, t1.x);
        unsigned cg1 = (t1.x == ku1) ? t1.y : 0xFFFFFFFFu;
        unsigned g1  = __reduce_min_sync(0xFFFFFFFFu, cg1);

        if (ku1 <= 0x80000000u) break;   // no positive score left (uniform)

        uint2 ent = (t1.x == ku1 && t1.y == g1) ? t2 : t1;
        unsigned ku2 = __reduce_max_sync(0xFFFFFFFFu, ent.x);
        unsigned cg2 = (ent.x == ku2) ? ent.y : 0xFFFFFFFFu;
        unsigned g2  = __reduce_min_sync(0xFFFFFFFFu, cg2);

        // locate records
        int s1 = -1, s2 = -1;
        if (e0.x == ku1 && e0.y == g1) s1 = lane;
        if (e1.x == ku1 && e1.y == g1) s1 = lane + 32;
        if (e2.x == ku1 && e2.y == g1) s1 = lane + 64;
        if (e3.x == ku1 && e3.y == g1) s1 = lane + 96;
        if (e0.x == ku2 && e0.y == g2) s2 = lane;
        if (e1.x == ku2 && e1.y == g2) s2 = lane + 32;
        if (e2.x == ku2 && e2.y == g2) s2 = lane + 64;
        if (e3.x == ku2 && e3.y == g2) s2 = lane + 96;
        unsigned bm1 = __ballot_sync(0xFFFFFFFFu, s1 >= 0);
        int slot1 = __shfl_sync(0xFFFFFFFFu, s1, __ffs(bm1) - 1);
        unsigned bm2 = __ballot_sync(0xFFFFFFFFu, s2 >= 0);
        int slot2 = bm2 ? __shfl_sync(0xFFFFFFFFu, s2, __ffs(bm2) - 1) : slot1;

        const Rec* w1 = &crec[p][slot1];
        float4 bb1 = make_float4(w1->y1, w1->x1, w1->y2, w1->x2);
        float  ba1 = w1->area;
        float  cl1 = w1->cls;
        const Rec* w2 = &crec[p][slot2];
        float4 bb2 = make_float4(w2->y1, w2->x1, w2->y2, w2->x2);
        float  ba2 = w2->area;

        // dual decision: w2 exists, there's room, and w2 survives w1's suppression
        bool dual = false;
        if (ku2 > 0x80000000u && (d + 1) < MAXDET) {
            float yy1 = fmaxf(bb1.x, bb2.x);
            float xx1 = fmaxf(bb1.y, bb2.y);
            float yy2 = fminf(bb1.z, bb2.z);
            float xx2 = fminf(bb1.w, bb2.w);
            float inter = fmaxf(yy2 - yy1, 0.0f) * fmaxf(xx2 - xx1, 0.0f);
            float S = ba1 + ba2;
            bool kill2 = inter > C_HI * S;
            if (!kill2 && !(inter < C_LO * S)) {
                float uni = ba1 + ba2 - inter;     // exact reference sequence
                if (uni > 0.0f) kill2 = (inter / uni) > 0.45f;
            }
            dual = !kill2;
        }

        ndet += dual ? 2 : 1;
        if (rank == 0 && tid == 0) {
            float s1f = (ku1 & 0x80000000u) ? __uint_as_float(ku1 & 0x7FFFFFFFu)
                                            : __uint_as_float(~ku1);
            ob[d * 4 + 0] = bb1.x; ob[d * 4 + 1] = bb1.y;
            ob[d * 4 + 2] = bb1.z; ob[d * 4 + 3] = bb1.w;
            oc[d]  = cl1;
            osc[d] = s1f;
            if (dual) {
                float s2f = (ku2 & 0x80000000u) ? __uint_as_float(ku2 & 0x7FFFFFFFu)
                                                : __uint_as_float(~ku2);
                ob[(d+1) * 4 + 0] = bb2.x; ob[(d+1) * 4 + 1] = bb2.y;
                ob[(d+1) * 4 + 2] = bb2.z; ob[(d+1) * 4 + 3] = bb2.w;
                oc[d+1]  = w2->cls;
                osc[d+1] = s2f;
            }
        }

        int dn = d + (dual ? 2 : 1);
        if (dn >= MAXDET) { d = dn; break; }   // uniform; no pass needed
        d = dn;

        // owner kills for selected anchors (pow2 threads: owner tid = l & 1023)
        {
            int l1 = (int)g1 - gbase;
            if ((unsigned)l1 < HALF_ANCH && (l1 & (NTHREADS - 1)) == tid)
                ukey[l1 >> 10] = 0u;
            if (dual) {
                int l2 = (int)g2 - gbase;
                if ((unsigned)l2 < HALF_ANCH && (l2 & (NTHREADS - 1)) == tid)
                    ukey[l2 >> 10] = 0u;
            }
        }

        // ---- fused suppress (vs 1 or 2 winners) + next local argmax ----
        lk = 0u;
        li = gbase + tid;
        #pragma unroll
        for (int k = KPT - 1; k >= 0; k--) {
            int l   = tid + k * NTHREADS;
            int gid = gbase + l;
            unsigned ku = ukey[k];
            if (ku != 0u) {
                float4 b  = sbox[l];
                float  ab = sarea[l];
                float yy1 = fmaxf(bb1.x, b.x);
                float xx1 = fmaxf(bb1.y, b.y);
                float yy2 = fminf(bb1.z, b.z);
                float xx2 = fminf(bb1.w, b.w);
                float inter = fmaxf(yy2 - yy1, 0.0f) * fmaxf(xx2 - xx1, 0.0f);
                float S = ba1 + ab;
                bool kill = inter > C_HI * S;
                if (!kill && !(inter < C_LO * S)) {
                    float uni = ba1 + ab - inter;
                    if (uni > 0.0f) kill = (inter / uni) > 0.45f;
                }
                if (dual && !kill) {
                    float zy1 = fmaxf(bb2.x, b.x);
                    float zx1 = fmaxf(bb2.y, b.y);
                    float zy2 = fminf(bb2.z, b.z);
                    float zx2 = fminf(bb2.w, b.w);
                    float in2 = fmaxf(zy2 - zy1, 0.0f) * fmaxf(zx2 - zx1, 0.0f);
                    float S2 = ba2 + ab;
                    bool k2 = in2 > C_HI * S2;
                    if (!k2 && !(in2 < C_LO * S2)) {
                        float uni2 = ba2 + ab - in2;
                        if (uni2 > 0.0f) k2 = (in2 / uni2) > 0.45f;
                    }
                    kill = k2;
                }
                if (kill) { ku = 0u; ukey[k] = 0u; }
            }
            if (ku >= lk) { lk = ku; li = gid; }
        }
    }

    if (rank == 0 && tid == 0) ond[img] = (float)ndet;

    asm volatile("barrier.cluster.arrive.aligned;" ::: "memory");
    asm volatile("barrier.cluster.wait.aligned;"   ::: "memory");
}

extern "C" void kernel_launch(void* const* d_in, const int* in_sizes, int n_in,
                              void* d_out, int out_size) {
    static bool attr_done = false;
    if (!attr_done) {
        cudaFuncSetAttribute(yolo_nms_kernel,
                             cudaFuncAttributeMaxDynamicSharedMemorySize, SMEM_BYTES);
        attr_done = true;
    }
    const float* in = (const float*)d_in[0];
    float* out = (float*)d_out;
    yolo_nms_kernel<<<BATCH * CLUSTER, NTHREADS, SMEM_BYTES>>>(in, out);
}

// round 14
// speedup vs baseline: 1.5799x; 1.1812x over previous
#include <cuda_runtime.h>
#include <float.h>
#include <cstdint>

#define NCH       36
#define NANCH     8400
#define NCLS      32
#define MAXDET    100
#define BATCH     64
#define NTHREADS  512
#define CLUSTER   2
#define HALF_ANCH 4200            // anchors per CTA
#define KPT       9               // ceil(4200/512)
#define CONF_T    0.25f
// iou > 0.45  <=>  inter > (0.45/1.45)*(A+B)   [valid: inter>0 => union>0]
#define C_HI      0.31034523f     // c*(1+~1.3e-6)
#define C_LO      0.31034442f     // c*(1-~1.3e-6)

// dynamic smem per CTA: float4 box[4200] + area[4200] + cls[4200]
#define SMEM_BYTES ((4 + 1 + 1) * HALF_ANCH * 4)

struct alignas(16) Rec {            // winner record (broadcast-read only)
    float y1, x1, y2, x2;
    float area, cls;
    float p0, p1;
};

__device__ __forceinline__ uint32_t smem_u32(const void* p) {
    uint32_t a;
    asm("{ .reg .u64 t; cvta.to.shared.u64 t, %1; cvt.u32.u64 %0, t; }" : "=r"(a) : "l"(p));
    return a;
}
__device__ __forceinline__ uint32_t mapa_u32(uint32_t a, uint32_t rank) {
    uint32_t o;
    asm("mapa.shared::cluster.u32 %0, %1, %2;" : "=r"(o) : "r"(a), "r"(rank));
    return o;
}
__device__ __forceinline__ void st_cluster(uint32_t a, unsigned v) {
    asm volatile("st.shared::cluster.u32 [%0], %1;" :: "r"(a), "r"(v) : "memory");
}
// monotone float -> u32 key (bigger float => bigger key); fkey(0.0f)=0x80000000
__device__ __forceinline__ unsigned fkey(float f) {
    unsigned b = __float_as_uint(f);
    return ((int)b >= 0) ? (b | 0x80000000u) : ~b;
}
__device__ __forceinline__ bool lexGT(uint2 a, uint2 b) {
    return (a.x > b.x) || (a.x == b.x && a.y < b.y);
}
// exact suppression decision: winner (wb, wa) vs anchor (b, ab); winner area first
__device__ __forceinline__ bool kill_test(float4 wb, float wa, float4 b, float ab) {
    float yy1 = fmaxf(wb.x, b.x);
    float xx1 = fmaxf(wb.y, b.y);
    float yy2 = fminf(wb.z, b.z);
    float xx2 = fminf(wb.w, b.w);
    float inter = fmaxf(yy2 - yy1, 0.0f) * fmaxf(xx2 - xx1, 0.0f);
    float S = wa + ab;
    bool kill = inter > C_HI * S;
    if (!kill && !(inter < C_LO * S)) {
        float uni = wa + ab - inter;   // exact reference sequence
        if (uni > 0.0f) kill = (inter / uni) > 0.45f;
    }
    return kill;
}

__global__ __launch_bounds__(NTHREADS, 1) __cluster_dims__(CLUSTER, 1, 1)
void yolo_nms_kernel(const float* __restrict__ in, float* __restrict__ out) {
    extern __shared__ float smem[];
    float4* sbox  = (float4*)smem;             // [4200]
    float*  sarea = smem + 4 * HALF_ANCH;      // [4200]
    float*  scls  = smem + 5 * HALF_ANCH;      // [4200]
    __shared__ uint2 ckey[2][128];             // parity x (4 winners x 32 warp-slots)
    __shared__ Rec   crec[2][128];
    __shared__ unsigned long long cbar;        // mbarrier, 32 arrivals/phase

    const int tid  = threadIdx.x;
    const int lane = tid & 31;
    const int wid  = tid >> 5;
    unsigned rank;
    asm("mov.u32 %0, %%cluster_ctarank;" : "=r"(rank));
    const int img   = blockIdx.x >> 1;
    const int gbase = rank * HALF_ANCH;

    const float* base = in + (size_t)img * NCH * NANCH;

    float* ob  = out + (size_t)img * MAXDET * 4;
    float* oc  = out + (size_t)BATCH * MAXDET * 4 + (size_t)img * MAXDET;
    float* osc = out + (size_t)BATCH * MAXDET * 4 + (size_t)BATCH * MAXDET + (size_t)img * MAXDET;
    float* ond = out + (size_t)BATCH * MAXDET * 4 + (size_t)BATCH * MAXDET * 2;

    const uint32_t bar_a  = smem_u32(&cbar);
    const uint32_t peer   = rank ^ 1u;
    const uint32_t r_bar  = mapa_u32(bar_a, peer);
    const uint32_t r_ckey = mapa_u32(smem_u32(&ckey[0][0]), peer);
    const uint32_t r_crec = mapa_u32(smem_u32(&crec[0][0]), peer);

    if (tid == 0) {
        asm volatile("mbarrier.init.shared.b64 [%0], %1;" :: "r"(bar_a), "r"(32u) : "memory");
    }

    if (rank == 0) {
        for (int i = tid; i < MAXDET * 4; i += NTHREADS) ob[i] = 0.0f;
        if (tid < MAXDET) { oc[tid] = 0.0f; osc[tid] = 0.0f; }
    }

    // ---- Phase 1: preprocess this CTA's 4200 anchors ----
    unsigned ukey[KPT];
    #pragma unroll
    for (int k = 0; k < KPT; k++) {
        int l = tid + k * NTHREADS;
        unsigned ku = 0u;
        if (l < HALF_ANCH) {
            int ga = gbase + l;
            float xc = base[0 * NANCH + ga];
            float yc = base[1 * NANCH + ga];
            float w  = base[2 * NANCH + ga];
            float h  = base[3 * NANCH + ga];
            float best = -FLT_MAX;
            int cls = 0;
            #pragma unroll
            for (int c = 0; c < NCLS; c++) {
                float v = base[(4 + c) * NANCH + ga];
                if (v > best) { best = v; cls = c; }   // strict > == first-max
            }
            float y1 = fminf(fmaxf(yc - 0.5f * h, 0.0f), 1.0f);
            float x1 = fminf(fmaxf(xc - 0.5f * w, 0.0f), 1.0f);
            float y2 = fminf(fmaxf(yc + 0.5f * h, 0.0f), 1.0f);
            float x2 = fminf(fmaxf(xc + 0.5f * w, 0.0f), 1.0f);
            sbox[l]  = make_float4(y1, x1, y2, x2);
            sarea[l] = (y2 - y1) * (x2 - x1);
            scls[l]  = (float)cls;
            if (best >= CONF_T) ku = fkey(best);   // masked anchors stay dead (ref: -1)
        }
        ukey[k] = ku;
    }
    __syncthreads();
    asm volatile("barrier.cluster.arrive.aligned;" ::: "memory");
    asm volatile("barrier.cluster.wait.aligned;"   ::: "memory");

    int ndet = 0, d = 0;
    for (int e = 0; e < MAXDET && d < MAXDET; e++) {
        const int p = e & 1;

        // ---- stage 1: per-warp top-4 (iterated redux; key desc, gid asc) ----
        unsigned tk[KPT];
        #pragma unroll
        for (int k = 0; k < KPT; k++) tk[k] = ukey[k];

        unsigned l2k = 0u; int l2i = gbase + tid; int l2w = 0;
        #pragma unroll
        for (int k = KPT - 1; k >= 0; k--) {
            int gid = gbase + tid + k * NTHREADS;
            if (tk[k] >= l2k) { l2k = tk[k]; l2i = gid; l2w = k; }
        }

        unsigned kk0, kk1, kk2, kk3, gg0, gg1, gg2, gg3;
        auto wextract = [&](unsigned& KJ, unsigned& GJ) {
            KJ = __reduce_max_sync(0xFFFFFFFFu, l2k);
            unsigned cc = (l2k == KJ) ? (unsigned)l2i : 0xFFFFFFFFu;
            GJ = __reduce_min_sync(0xFFFFFFFFu, cc);
            if (l2k == KJ && (unsigned)l2i == GJ) {
                #pragma unroll
                for (int k = 0; k < KPT; k++) if (k == l2w) tk[k] = 0u;
                l2k = 0u; l2i = gbase + tid; l2w = 0;
                #pragma unroll
                for (int k = KPT - 1; k >= 0; k--) {
                    int gid = gbase + tid + k * NTHREADS;
                    if (tk[k] >= l2k) { l2k = tk[k]; l2i = gid; l2w = k; }
                }
            }
        };
        wextract(kk0, gg0); wextract(kk1, gg1); wextract(kk2, gg2); wextract(kk3, gg3);

        // ---- publish 4 candidates + records to BOTH CTAs, 2 arrives (lane 0) ----
        if (lane == 0) {
            auto pub = [&](int j, unsigned KJ, unsigned GJ) {
                int l = (int)GJ - gbase;
                if ((unsigned)l >= HALF_ANCH) l = 0;   // dead-entry clamp; data unused
                float4 bx = sbox[l]; float aa = sarea[l]; float cl2 = scls[l];
                int slot = j * 32 + (int)rank * 16 + wid;
                ckey[p][slot] = make_uint2(KJ, GJ);
                Rec r; r.y1 = bx.x; r.x1 = bx.y; r.y2 = bx.z; r.x2 = bx.w;
                r.area = aa; r.cls = cl2; r.p0 = 0.f; r.p1 = 0.f;
                crec[p][slot] = r;
                uint32_t rk = r_ckey + (uint32_t)(p * 128 + slot) * 8u;
                st_cluster(rk + 0, KJ);
                st_cluster(rk + 4, GJ);
                uint32_t rr = r_crec + (uint32_t)(p * 128 + slot) * 32u;
                st_cluster(rr + 0,  __float_as_uint(bx.x));
                st_cluster(rr + 4,  __float_as_uint(bx.y));
                st_cluster(rr + 8,  __float_as_uint(bx.z));
                st_cluster(rr + 12, __float_as_uint(bx.w));
                st_cluster(rr + 16, __float_as_uint(aa));
                st_cluster(rr + 20, __float_as_uint(cl2));
            };
            pub(0, kk0, gg0); pub(1, kk1, gg1); pub(2, kk2, gg2); pub(3, kk3, gg3);
            asm volatile("mbarrier.arrive.shared.b64 _, [%0];" :: "r"(bar_a) : "memory");
            asm volatile("mbarrier.arrive.release.cluster.shared::cluster.b64 _, [%0];"
                         :: "r"(r_bar) : "memory");
        }

        // ---- wait: 32 arrivals (16 local + 16 remote) ----
        {
            unsigned done;
            asm volatile(
                "{\n\t.reg .pred q;\n\t"
                "mbarrier.try_wait.parity.acquire.cluster.shared::cta.b64 q, [%1], %2, 0x989680;\n\t"
                "selp.b32 %0, 1, 0, q;\n\t}"
                : "=r"(done) : "r"(bar_a), "r"((unsigned)p) : "memory");
            if (!done) {
                asm volatile(
                    "{\n\t.reg .pred Q1;\n\t"
                    "WL_%=:\n\t"
                    "mbarrier.try_wait.parity.acquire.cluster.shared::cta.b64 Q1, [%0], %1, 0x989680;\n\t"
                    "@Q1 bra.uni WD_%=;\n\t"
                    "bra.uni WL_%=;\n\t"
                    "WD_%=:\n\t}"
                    :: "r"(bar_a), "r"((unsigned)p) : "memory");
            }
        }

        // ---- stage 2: global top-4 of 128 candidates (4/lane) ----
        uint2 q0 = ckey[p][lane];
        uint2 q1 = ckey[p][lane + 32];
        uint2 q2 = ckey[p][lane + 64];
        uint2 q3 = ckey[p][lane + 96];
        unsigned K0, K1, K2, K3, G0, G1, G2, G3;
        int S0, S1, S2, S3;
        auto gextract = [&](unsigned& KJ, unsigned& GJ, int& SJ) {
            uint2 lb = q0; int lm = 0;
            if (lexGT(q1, lb)) { lb = q1; lm = 1; }
            if (lexGT(q2, lb)) { lb = q2; lm = 2; }
            if (lexGT(q3, lb)) { lb = q3; lm = 3; }
            KJ = __reduce_max_sync(0xFFFFFFFFu, lb.x);
            unsigned cg = (lb.x == KJ) ? lb.y : 0xFFFFFFFFu;
            GJ = __reduce_min_sync(0xFFFFFFFFu, cg);
            bool hit = (lb.x == KJ) && (lb.y == GJ);
            unsigned bm = __ballot_sync(0xFFFFFFFFu, hit);
            int ls2 = lane + 32 * lm;
            SJ = __shfl_sync(0xFFFFFFFFu, ls2, __ffs(bm) - 1);
            if (hit) {
                if (lm == 0) q0 = make_uint2(0u, 0xFFFFFFFFu);
                else if (lm == 1) q1 = make_uint2(0u, 0xFFFFFFFFu);
                else if (lm == 2) q2 = make_uint2(0u, 0xFFFFFFFFu);
                else q3 = make_uint2(0u, 0xFFFFFFFFu);
            }
        };
        gextract(K0, G0, S0); gextract(K1, G1, S1);
        gextract(K2, G2, S2); gextract(K3, G3, S3);

        if (K0 <= 0x80000000u) break;   // no positive score anywhere (uniform)

        Rec wr0 = crec[p][S0]; Rec wr1 = crec[p][S1];
        Rec wr2 = crec[p][S2]; Rec wr3 = crec[p][S3];
        float4 wb0 = make_float4(wr0.y1, wr0.x1, wr0.y2, wr0.x2); float wa0 = wr0.area;
        float4 wb1 = make_float4(wr1.y1, wr1.x1, wr1.y2, wr1.x2); float wa1 = wr1.area;
        float4 wb2 = make_float4(wr2.y1, wr2.x1, wr2.y2, wr2.x2); float wa2 = wr2.area;
        float4 wb3 = make_float4(wr3.y1, wr3.x1, wr3.y2, wr3.x2); float wa3 = wr3.area;

        // ---- greedy-prefix emission over the sorted top-4 (exact arithmetic) ----
        unsigned emask = 1u;    // c1 always emitted (K0 positive, d < MAXDET)
        int cnt = 1;
        if (K1 > 0x80000000u && d + cnt < MAXDET) {
            bool kd = kill_test(wb0, wa0, wb1, wa1);
            if (!kd) { emask |= 2u; cnt++; }
        }
        if (K2 > 0x80000000u && d + cnt < MAXDET) {
            bool kd = kill_test(wb0, wa0, wb2, wa2);
            if (!kd && (emask & 2u)) kd = kill_test(wb1, wa1, wb2, wa2);
            if (!kd) { emask |= 4u; cnt++; }
        }
        if (K3 > 0x80000000u && d + cnt < MAXDET) {
            bool kd = kill_test(wb0, wa0, wb3, wa3);
            if (!kd && (emask & 2u)) kd = kill_test(wb1, wa1, wb3, wa3);
            if (!kd && (emask & 4u)) kd = kill_test(wb2, wa2, wb3, wa3);
            if (!kd) { emask |= 8u; cnt++; }
        }
        ndet += cnt;

        if (rank == 0 && tid == 0) {
            auto wout = [&](int dd, float4 bb, float cl2, unsigned KJ) {
                float s = (KJ & 0x80000000u) ? __uint_as_float(KJ & 0x7FFFFFFFu)
                                             : __uint_as_float(~KJ);
                ob[dd * 4 + 0] = bb.x; ob[dd * 4 + 1] = bb.y;
                ob[dd * 4 + 2] = bb.z; ob[dd * 4 + 3] = bb.w;
                oc[dd] = cl2; osc[dd] = s;
            };
            int dd = d;
            if (emask & 1u) { wout(dd, wb0, wr0.cls, K0); dd++; }
            if (emask & 2u) { wout(dd, wb1, wr1.cls, K1); dd++; }
            if (emask & 4u) { wout(dd, wb2, wr2.cls, K2); dd++; }
            if (emask & 8u) { wout(dd, wb3, wr3.cls, K3); dd++; }
        }

        d += cnt;
        if (d >= MAXDET) break;   // uniform; no pass needed

        // inert-ify non-emitted candidates: box outside [0,1], area 0 kills nothing
        if (!(emask & 2u)) { wb1 = make_float4(2.f, 2.f, 2.f, 2.f); wa1 = 0.f; }
        if (!(emask & 4u)) { wb2 = make_float4(2.f, 2.f, 2.f, 2.f); wa2 = 0.f; }
        if (!(emask & 8u)) { wb3 = make_float4(2.f, 2.f, 2.f, 2.f); wa3 = 0.f; }

        // owner kills for emitted anchors (pow2 threads: owner tid = l & 511)
        auto okill = [&](unsigned gj, unsigned bit) {
            if (emask & bit) {
                int l = (int)gj - gbase;
                if ((unsigned)l < HALF_ANCH && (l & (NTHREADS - 1)) == tid) {
                    int kw = l >> 9;
                    #pragma unroll
                    for (int k = 0; k < KPT; k++) if (k == kw) ukey[k] = 0u;
                }
            }
        };
        okill(G0, 1u); okill(G1, 2u); okill(G2, 4u); okill(G3, 8u);

        // ---- fused suppress vs up to 4 winners (branch-free over winners) ----
        #pragma unroll
        for (int k = 0; k < KPT; k++) {
            unsigned ku = ukey[k];
            if (ku != 0u) {
                int l = tid + k * NTHREADS;
                float4 b  = sbox[l];
                float  ab = sarea[l];
                bool kl = kill_test(wb0, wa0, b, ab);
                kl = kl | kill_test(wb1, wa1, b, ab);
                kl = kl | kill_test(wb2, wa2, b, ab);
                kl = kl | kill_test(wb3, wa3, b, ab);
                if (kl) ukey[k] = 0u;
            }
        }
    }

    if (rank == 0 && tid == 0) ond[img] = (float)ndet;

    asm volatile("barrier.cluster.arrive.aligned;" ::: "memory");
    asm volatile("barrier.cluster.wait.aligned;"   ::: "memory");
}

extern "C" void kernel_launch(void* const* d_in, const int* in_sizes, int n_in,
                              void* d_out, int out_size) {
    static bool attr_done = false;
    if (!attr_done) {
        cudaFuncSetAttribute(yolo_nms_kernel,
                             cudaFuncAttributeMaxDynamicSharedMemorySize, SMEM_BYTES);
        attr_done = true;
    }
    const float* in = (const float*)d_in[0];
    float* out = (float*)d_out;
    yolo_nms_kernel<<<BATCH * CLUSTER, NTHREADS, SMEM_BYTES>>>(in, out);
}